// round 7
// baseline (speedup 1.0000x reference)
#include <cuda_runtime.h>
#include <cuda_bf16.h>
#include <cstdint>

#define N_ATOM 50000
#define M_NBR  12
#define NM_TOT 600000
#define F_DIM  128
#define FAN_IN 320
#define EPS    1e-5f
#define CH     25

// ---------------- scratch ----------------------------------------------------
__device__ __align__(16) float g_SA[(size_t)N_ATOM * 512];      // [n][0:256)=S, [256:512)=A
__device__ __align__(16) float g_gated[(size_t)NM_TOT * 256];
__device__ __align__(16) float g_nbr[(size_t)N_ATOM * F_DIM];
__device__ float g_stats1[512];
__device__ float g_stats2[256];
__device__ float g_bn1[512];
__device__ float g_bn2[256];
__device__ int   g_idx32[NM_TOT];
__device__ int   g_is64;
__device__ __align__(16) __nv_bfloat16 g_Wh[256 * 64];   // W_edge hi, K-major
__device__ __align__(16) __nv_bfloat16 g_Wl[256 * 64];   // W_edge lo

__device__ __forceinline__ float softplusf(float x) {
    return fmaxf(x, 0.f) + log1pf(__expf(-fabsf(x)));
}
__device__ __forceinline__ float sigmoidf(float x) {
    return 1.f / (1.f + __expf(-x));
}
__device__ __forceinline__ uint32_t smem_u32(const void* p) {
    uint32_t a;
    asm("{ .reg .u64 t; cvta.to.shared.u64 t, %1; cvt.u32.u64 %0, t; }"
        : "=r"(a) : "l"(p));
    return a;
}
__device__ __forceinline__ uint32_t pkbf(__nv_bfloat16 a, __nv_bfloat16 b) {
    __nv_bfloat162 t = __halves2bfloat162(a, b);
    return *(uint32_t*)&t;
}
__device__ __forceinline__ void ldsm_x4(uint32_t* r, uint32_t addr) {
    asm volatile("ldmatrix.sync.aligned.m8n8.x4.shared.b16 {%0,%1,%2,%3}, [%4];"
        : "=r"(r[0]), "=r"(r[1]), "=r"(r[2]), "=r"(r[3]) : "r"(addr));
}
__device__ __forceinline__ void mma_bf16(float* c, const uint32_t* a,
                                         uint32_t b0, uint32_t b1) {
    asm volatile("mma.sync.aligned.m16n8k16.row.col.f32.bf16.bf16.f32 "
        "{%0,%1,%2,%3}, {%4,%5,%6,%7}, {%8,%9}, {%0,%1,%2,%3};"
        : "+f"(c[0]), "+f"(c[1]), "+f"(c[2]), "+f"(c[3])
        : "r"(a[0]), "r"(a[1]), "r"(a[2]), "r"(a[3]), "r"(b0), "r"(b1));
}

// smem byte layout for k_gate_hmma (dynamic)
#define SM_BIAS 0          // 128 floats (512 B)
#define SM_STAT 512        // 256 floats (1024 B)
#define SM_A    2048       // 128 rows x 24 chunks x 16B = 49152
#define SM_W    51200      // 128 rows x 24 chunks x 16B = 49152
#define SM_TOTAL 100352

// ---------------- k_detect ---------------------------------------------------
__global__ void k_detect(const int* __restrict__ raw) {
    __shared__ int any;
    if (threadIdx.x == 0) any = 0;
    __syncthreads();
    if (raw[threadIdx.x * 2 + 1] != 0) atomicOr(&any, 1);
    __syncthreads();
    if (threadIdx.x == 0) g_is64 = any ? 0 : 1;
}

// ---------------- k_convert --------------------------------------------------
__global__ void k_convert(const int* __restrict__ raw) {
    int i = blockIdx.x * blockDim.x + threadIdx.x;
    if (i < NM_TOT) g_idx32[i] = g_is64 ? raw[2 * i] : raw[i];
    if (i < 512) g_stats1[i] = 0.f;
    if (i < 256) g_stats2[i] = 0.f;
}

// ---------------- k_wconv: split W_edge into bf16 hi/lo ----------------------
__global__ void k_wconv(const float* __restrict__ W) {
    int i = blockIdx.x * blockDim.x + threadIdx.x;
    if (i < 256 * 64) {
        int f = i >> 6, k = i & 63;
        float w = W[f * FAN_IN + 256 + k];
        __nv_bfloat16 h = __float2bfloat16(w);
        g_Wh[i] = h;
        g_Wl[i] = __float2bfloat16(w - __bfloat162float(h));
    }
}

// ---------------- k1: [S|A] = atom @ [W_self|W_nbr]^T (proven scalar) --------
__global__ __launch_bounds__(256) void k_gemm_sa(const float* __restrict__ atom,
                                                 const float* __restrict__ W) {
    __shared__ float Xs[64][64];
    __shared__ float Ws[64][128];
    const int tid = threadIdx.x;
    const int tx = tid & 31, ty = tid >> 5;
    const int fbase = blockIdx.x * 128;
    const int row0  = blockIdx.y * 64;
    const int wfbase = (blockIdx.x < 2) ? fbase : fbase - 256;
    const int wkoff  = (blockIdx.x < 2) ? 0 : 128;

    float c[8][4];
#pragma unroll
    for (int i = 0; i < 8; i++)
#pragma unroll
        for (int j = 0; j < 4; j++) c[i][j] = 0.f;

    for (int kc = 0; kc < 128; kc += 64) {
        for (int t = tid; t < 64 * 16; t += 256) {
            int r = t >> 4, kq = t & 15;
            int gr = row0 + r;
            float4 v = make_float4(0.f, 0.f, 0.f, 0.f);
            if (gr < N_ATOM)
                v = *(const float4*)(atom + (size_t)gr * 128 + kc + kq * 4);
            *(float4*)&Xs[r][kq * 4] = v;
        }
        for (int t = tid; t < 128 * 16; t += 256) {
            int fl = t & 127, kq = t >> 7;
            float4 v = *(const float4*)(W + (size_t)(wfbase + fl) * FAN_IN + wkoff + kc + kq * 4);
            Ws[kq * 4 + 0][fl] = v.x; Ws[kq * 4 + 1][fl] = v.y;
            Ws[kq * 4 + 2][fl] = v.z; Ws[kq * 4 + 3][fl] = v.w;
        }
        __syncthreads();
#pragma unroll 8
        for (int k = 0; k < 64; k++) {
            float4 b = *(float4*)&Ws[k][tx * 4];
#pragma unroll
            for (int i = 0; i < 8; i++) {
                float a = Xs[ty * 8 + i][k];
                c[i][0] += a * b.x; c[i][1] += a * b.y;
                c[i][2] += a * b.z; c[i][3] += a * b.w;
            }
        }
        __syncthreads();
    }
#pragma unroll
    for (int i = 0; i < 8; i++) {
        int gr = row0 + ty * 8 + i;
        if (gr < N_ATOM)
            *(float4*)(g_SA + (size_t)gr * 512 + fbase + tx * 4) =
                make_float4(c[i][0], c[i][1], c[i][2], c[i][3]);
    }
}

// ---------------- k2: E GEMM via mma.sync bf16 hi/lo, fused gate epilogue ----
// grid (2, 4688), 256 threads (8 warps). CTA tile 128 rows x 128 cols, K'=192.
// A smem = [Xh | Xh | Xl], W smem = [Wh | Wl | Wh]  (24 chunks of 16B per row,
// chunk index XOR-swizzled by row&7). Warp w: rows w*16..+15, all 128 cols.
__global__ __launch_bounds__(256) void k_gate_hmma(const float* __restrict__ nbr,
                                                   const float* __restrict__ bias) {
    extern __shared__ char smem[];
    const uint32_t sb = smem_u32(smem);
    const int tid = threadIdx.x;
    const int wid = tid >> 5, lane = tid & 31;
    const int fbase = blockIdx.x * 128;
    const int row0  = blockIdx.y * 128;
    const int rw0 = wid * 16;

    // init bias + stats
    if (tid < 128) *(float*)(smem + SM_BIAS + tid * 4) = bias[fbase + tid];
    for (int t = tid; t < 256; t += 256) *(float*)(smem + SM_STAT + t * 4) = 0.f;

    // ---- fill A tile: rows 0..127, source chunks c=0..7 (8 bf16 = 16B) ----
    for (int t = tid; t < 1024; t += 256) {
        int r = t >> 3, c = t & 7;
        int gr = row0 + r; if (gr >= NM_TOT) gr = NM_TOT - 1;
        float4 v0 = *(const float4*)(nbr + (size_t)gr * 64 + c * 8);
        float4 v1 = *(const float4*)(nbr + (size_t)gr * 64 + c * 8 + 4);
        float xs[8] = {v0.x, v0.y, v0.z, v0.w, v1.x, v1.y, v1.z, v1.w};
        __nv_bfloat16 h[8]; float l[8];
#pragma unroll
        for (int q = 0; q < 8; q++) {
            h[q] = __float2bfloat16(xs[q]);
            l[q] = xs[q] - __bfloat162float(h[q]);
        }
        uint4 hh = make_uint4(pkbf(h[0], h[1]), pkbf(h[2], h[3]),
                              pkbf(h[4], h[5]), pkbf(h[6], h[7]));
        uint4 ll = make_uint4(
            pkbf(__float2bfloat16(l[0]), __float2bfloat16(l[1])),
            pkbf(__float2bfloat16(l[2]), __float2bfloat16(l[3])),
            pkbf(__float2bfloat16(l[4]), __float2bfloat16(l[5])),
            pkbf(__float2bfloat16(l[6]), __float2bfloat16(l[7])));
        int off = r * 384 + ((c ^ (r & 7)) << 4);
        *(uint4*)(smem + SM_A + off)       = hh;   // chunks 0..7  : Xh
        *(uint4*)(smem + SM_A + off + 128) = hh;   // chunks 8..15 : Xh
        *(uint4*)(smem + SM_A + off + 256) = ll;   // chunks 16..23: Xl
    }
    // ---- fill W tile: rows = local feature 0..127 ----
    for (int t = tid; t < 1024; t += 256) {
        int r = t >> 3, c = t & 7;
        int gf = fbase + r;
        uint4 hh = *(const uint4*)((const char*)g_Wh + (size_t)gf * 128 + c * 16);
        uint4 ll = *(const uint4*)((const char*)g_Wl + (size_t)gf * 128 + c * 16);
        int off = r * 384 + ((c ^ (r & 7)) << 4);
        *(uint4*)(smem + SM_W + off)       = hh;   // Wh
        *(uint4*)(smem + SM_W + off + 128) = ll;   // Wl
        *(uint4*)(smem + SM_W + off + 256) = hh;   // Wh
    }
    __syncthreads();

    // ---- mainloop: 12 k16-steps over K'=192 ----
    float acc[16][4];
#pragma unroll
    for (int i = 0; i < 16; i++)
#pragma unroll
        for (int j = 0; j < 4; j++) acc[i][j] = 0.f;

#pragma unroll
    for (int ks = 0; ks < 12; ks++) {
        uint32_t a[4];
        {
            int arow = rw0 + (lane & 15);
            int ac = ks * 2 + (lane >> 4);
            ldsm_x4(a, sb + SM_A + arow * 384 + ((ac ^ (arow & 7)) << 4));
        }
        int brow_l = ((lane >> 4) << 3) + (lane & 7);
        int bc = ks * 2 + ((lane >> 3) & 1);
#pragma unroll
        for (int t = 0; t < 8; t++) {
            uint32_t b[4];
            int brow = t * 16 + brow_l;
            ldsm_x4(b, sb + SM_W + brow * 384 + ((bc ^ (brow & 7)) << 4));
            mma_bf16(acc[2 * t],     a, b[0], b[1]);
            mma_bf16(acc[2 * t + 1], a, b[2], b[3]);
        }
    }

    // ---- epilogue ----
    const int g = lane >> 2, tig = lane & 3;
    float* s_stat = (float*)(smem + SM_STAT);

    int nn[2], jj[2]; float mk[2]; bool val[2];
#pragma unroll
    for (int rr = 0; rr < 2; rr++) {
        int nm = row0 + rw0 + g + rr * 8;
        val[rr] = (nm < NM_TOT);
        int nmc = val[rr] ? nm : 0;
        nn[rr] = nmc / 12;
        jj[rr] = g_idx32[nmc];
        mk[rr] = (val[rr] && jj[rr] != 0) ? 1.f : 0.f;
    }

#pragma unroll
    for (int nt = 0; nt < 16; nt++) {
        int lcol = nt * 8 + tig * 2;           // local col 0..127
        int col = fbase + lcol;
        float2 b2 = *(const float2*)(smem + SM_BIAS + lcol * 4);
        float S0 = 0.f, S1 = 0.f, Q0 = 0.f, Q1 = 0.f;
#pragma unroll
        for (int rr = 0; rr < 2; rr++) {
            if (!val[rr]) continue;
            int nm = row0 + rw0 + g + rr * 8;
            float2 s2 = *(const float2*)(g_SA + (size_t)nn[rr] * 512 + col);
            float2 a2 = *(const float2*)(g_SA + (size_t)jj[rr] * 512 + 256 + col);
            float g0 = s2.x + b2.x + mk[rr] * (a2.x + acc[nt][rr * 2 + 0]);
            float g1 = s2.y + b2.y + mk[rr] * (a2.y + acc[nt][rr * 2 + 1]);
            *(float2*)(g_gated + (size_t)nm * 256 + col) = make_float2(g0, g1);
            S0 += g0; S1 += g1; Q0 += g0 * g0; Q1 += g1 * g1;
        }
        // reduce across the 8 g-lanes (lane bits 2,3,4)
#pragma unroll
        for (int s = 4; s <= 16; s <<= 1) {
            S0 += __shfl_xor_sync(0xffffffffu, S0, s);
            S1 += __shfl_xor_sync(0xffffffffu, S1, s);
            Q0 += __shfl_xor_sync(0xffffffffu, Q0, s);
            Q1 += __shfl_xor_sync(0xffffffffu, Q1, s);
        }
        if (lane < 4) {
            atomicAdd(&s_stat[lcol],           S0);
            atomicAdd(&s_stat[lcol + 1],       S1);
            atomicAdd(&s_stat[128 + lcol],     Q0);
            atomicAdd(&s_stat[128 + lcol + 1], Q1);
        }
    }
    __syncthreads();
    if (tid < 128)      atomicAdd(&g_stats1[fbase + tid],             s_stat[tid]);
    else if (tid < 256) atomicAdd(&g_stats1[256 + fbase + tid - 128], s_stat[tid]);
}

// ---------------- k3: finalize BN1 affine ------------------------------------
__global__ void k_fin1(const float* __restrict__ gamma1, const float* __restrict__ beta1) {
    int f = threadIdx.x;  // 256
    float inv = 1.f / (float)NM_TOT;
    float mean = g_stats1[f] * inv;
    float var  = g_stats1[256 + f] * inv - mean * mean;
    float sc = gamma1[f] * rsqrtf(var + EPS);
    g_bn1[f] = sc;
    g_bn1[256 + f] = beta1[f] - mean * sc;
}

// ---------------- k4: gate + sum over M + BN2 stats --------------------------
__global__ __launch_bounds__(128) void k_reduce() {
    const int f = threadIdx.x;
    const int n0 = blockIdx.x * CH;
    const float sc_f = g_bn1[f],        sh_f = g_bn1[256 + f];
    const float sc_c = g_bn1[128 + f],  sh_c = g_bn1[256 + 128 + f];
    float bs = 0.f, bq = 0.f;
    for (int n = n0; n < n0 + CH; n++) {
        float acc = 0.f;
#pragma unroll
        for (int m = 0; m < 12; m++) {
            int nm = n * 12 + m;
            int j = g_idx32[nm];
            if (j != 0) {
                float gf = g_gated[(size_t)nm * 256 + f]       * sc_f + sh_f;
                float gc = g_gated[(size_t)nm * 256 + 128 + f] * sc_c + sh_c;
                acc += sigmoidf(gf) * softplusf(gc);
            }
        }
        g_nbr[(size_t)n * 128 + f] = acc;
        bs += acc; bq += acc * acc;
    }
    atomicAdd(&g_stats2[f],       bs);
    atomicAdd(&g_stats2[128 + f], bq);
}

// ---------------- k5: finalize BN2 affine ------------------------------------
__global__ void k_fin2(const float* __restrict__ gamma2, const float* __restrict__ beta2) {
    int f = threadIdx.x;  // 128
    float inv = 1.f / (float)N_ATOM;
    float mean = g_stats2[f] * inv;
    float var  = g_stats2[128 + f] * inv - mean * mean;
    float sc = gamma2[f] * rsqrtf(var + EPS);
    g_bn2[f] = sc;
    g_bn2[128 + f] = beta2[f] - mean * sc;
}

// ---------------- k6: out = softplus(atom + BN2(nbr_sumed)) ------------------
__global__ void k_out(const float* __restrict__ atom, float* __restrict__ out) {
    int i = blockIdx.x * blockDim.x + threadIdx.x;
    if (i < N_ATOM * 128) {
        int f = i & 127;
        float v = atom[i] + g_nbr[i] * g_bn2[f] + g_bn2[128 + f];
        out[i] = softplusf(v);
    }
}

// ---------------- launch ------------------------------------------------------
extern "C" void kernel_launch(void* const* d_in, const int* in_sizes, int n_in,
                              void* d_out, int out_size) {
    const float* atom   = (const float*)d_in[0];
    const float* nbr    = (const float*)d_in[1];
    const int*   idxraw = (const int*)d_in[2];
    const float* W      = (const float*)d_in[3];
    const float* b      = (const float*)d_in[4];
    const float* gamma1 = (const float*)d_in[5];
    const float* beta1  = (const float*)d_in[6];
    const float* gamma2 = (const float*)d_in[7];
    const float* beta2  = (const float*)d_in[8];
    float* out = (float*)d_out;

    cudaFuncSetAttribute(k_gate_hmma, cudaFuncAttributeMaxDynamicSharedMemorySize, SM_TOTAL);

    k_detect<<<1, 256>>>(idxraw);
    k_convert<<<(NM_TOT + 255) / 256, 256>>>(idxraw);
    k_wconv<<<64, 256>>>(W);
    k_gemm_sa<<<dim3(4, (N_ATOM + 63) / 64), 256>>>(atom, W);
    k_gate_hmma<<<dim3(2, (NM_TOT + 127) / 128), 256, SM_TOTAL>>>(nbr, b);
    k_fin1<<<1, 256>>>(gamma1, beta1);
    k_reduce<<<N_ATOM / CH, 128>>>();
    k_fin2<<<1, 128>>>(gamma2, beta2);
    k_out<<<(N_ATOM * 128 + 255) / 256, 256>>>(atom, out);
}